// round 15
// baseline (speedup 1.0000x reference)
#include <cuda_runtime.h>
#include <cuda_fp16.h>
#include <cstdint>

// ---------------- problem constants ----------------
#define B_    4
#define L_    1024
#define N_    2048
#define VD_   512
#define LD_   768
#define HID_  512
#define H_    8
#define HD_   64
#define SCALE_ 0.125f
#define LOG2E_ 1.4426950408889634f

// ---------------- scratch ----------------
__device__ __half g_qh  [(size_t)B_ * L_ * HID_];
__device__ __half g_kh  [(size_t)B_ * N_ * HID_];
__device__ __half g_vth [(size_t)B_ * H_ * HD_ * N_];   // V^T [b][h][d][n]
__device__ __half g_aoh [(size_t)B_ * L_ * HID_];
__device__ __half g_xh  [(size_t)B_ * L_ * VD_];
__device__ __half g_vfh [(size_t)B_ * N_ * LD_];
__device__ __half g_wqh [(size_t)HID_ * VD_];
__device__ __half g_wkvh[(size_t)2 * HID_ * LD_];
__device__ __half g_wph [(size_t)VD_ * HID_];

// ---------------- helpers ----------------
__device__ __forceinline__ float ex2(float x) {
    float y;
    asm("ex2.approx.f32 %0, %1;" : "=f"(y) : "f"(x));
    return y;
}

__device__ __forceinline__ uint32_t pack_h2(float lo, float hi) {
    __half2 h = __floats2half2_rn(lo, hi);
    return *reinterpret_cast<uint32_t*>(&h);
}

__device__ __forceinline__ void mma_f16(float* c, const uint32_t* a, const uint32_t* b) {
    asm volatile(
        "mma.sync.aligned.m16n8k16.row.col.f32.f16.f16.f32 "
        "{%0,%1,%2,%3}, {%4,%5,%6,%7}, {%8,%9}, {%0,%1,%2,%3};"
        : "+f"(c[0]), "+f"(c[1]), "+f"(c[2]), "+f"(c[3])
        : "r"(a[0]), "r"(a[1]), "r"(a[2]), "r"(a[3]), "r"(b[0]), "r"(b[1]));
}

__device__ __forceinline__ void ldsm_x4(uint32_t* r, uint32_t saddr) {
    asm volatile("ldmatrix.sync.aligned.m8n8.x4.shared.b16 {%0,%1,%2,%3}, [%4];"
                 : "=r"(r[0]), "=r"(r[1]), "=r"(r[2]), "=r"(r[3]) : "r"(saddr));
}

__device__ __forceinline__ void cp16(uint32_t dst, const void* src) {
    asm volatile("cp.async.cg.shared.global [%0], [%1], 16;" :: "r"(dst), "l"(src));
}
__device__ __forceinline__ void cp_commit() { asm volatile("cp.async.commit_group;"); }
template <int Np>
__device__ __forceinline__ void cp_wait() {
    asm volatile("cp.async.wait_group %0;" :: "n"(Np) : "memory");
}

// ======================================================================
// Prepass: round inputs/weights to fp16 once.
// ======================================================================
#define PN0 524288
#define PN1 1572864
#define PN2 65536
#define PN3 196608
#define PN4 65536
#define PNT (PN0 + PN1 + PN2 + PN3 + PN4)

__global__ void __launch_bounds__(256)
prepass_kernel(const float4* __restrict__ x,  const float4* __restrict__ vf,
               const float4* __restrict__ wq, const float4* __restrict__ wkv,
               const float4* __restrict__ wp,
               uint2* __restrict__ xh,  uint2* __restrict__ vfh,
               uint2* __restrict__ wqh, uint2* __restrict__ wkvh,
               uint2* __restrict__ wph)
{
    for (int i = blockIdx.x * blockDim.x + threadIdx.x; i < PNT;
         i += gridDim.x * blockDim.x) {
        const float4* s; uint2* d; int off;
        if (i < PN0)                   { s = x;   d = xh;   off = i; }
        else if (i < PN0+PN1)          { s = vf;  d = vfh;  off = i - PN0; }
        else if (i < PN0+PN1+PN2)      { s = wq;  d = wqh;  off = i - PN0 - PN1; }
        else if (i < PN0+PN1+PN2+PN3)  { s = wkv; d = wkvh; off = i - PN0 - PN1 - PN2; }
        else                           { s = wp;  d = wph;  off = i - PN0 - PN1 - PN2 - PN3; }
        float4 v = s[off];
        uint2 o;
        o.x = pack_h2(v.x, v.y);
        o.y = pack_h2(v.z, v.w);
        d[off] = o;
    }
}

// ======================================================================
// fp16 GEMM: 128x128 tile, 64-half K-stages, cp.async 3-STAGE pipeline,
// m16n8k16, HSTR=72, ldmatrix fragments.
// mode 0: fp32 out + bias; 1: fp16 out; 2: KV split (K fp16 / V^T fp16).
// ======================================================================
#define HSTR 72
#define HGBK 64
#define HSTAGE (128 * HSTR)
#define HSTAGES 3
#define HGEMM_SMEM (HSTAGES * 2 * HSTAGE * 2)   // 110592 bytes

__device__ __forceinline__ void gemm_h_body(
    const __half* __restrict__ A, const __half* __restrict__ W,
    int K, float alpha, int mode,
    float* __restrict__ Cf, __half* __restrict__ ChQ,
    __half* __restrict__ ChK, __half* __restrict__ CvtH,
    const float* __restrict__ bias,
    int bm0, int bn0)
{
    extern __shared__ char smc[];
    const uint32_t sbase = (uint32_t)__cvta_generic_to_shared(smc);
    const uint32_t sA = sbase;                              // stages 0..2
    const uint32_t sB = sbase + HSTAGES * HSTAGE * 2;       // stages 0..2

    const int tid  = threadIdx.x;
    const int lane = tid & 31;
    const int w    = tid >> 5;
    const int g    = lane >> 2;
    const int t4   = lane & 3;
    const int wm   = w >> 2;
    const int wn   = w & 3;
    const int KT   = K / HGBK;
    const int lm   = lane >> 3;
    const int lj   = lane & 7;

    float acc[4][4][4];
    #pragma unroll
    for (int mi = 0; mi < 4; mi++)
        #pragma unroll
        for (int ni = 0; ni < 4; ni++)
            #pragma unroll
            for (int j = 0; j < 4; j++) acc[mi][ni][j] = 0.f;

    auto issue = [&](int kt, int st) {
        const int k0 = kt * HGBK;
        #pragma unroll
        for (int i = 0; i < 4; i++) {
            int c   = tid + 256 * i;
            int row = c >> 3;
            int seg = c & 7;
            cp16(sA + (uint32_t)((st * HSTAGE + row * HSTR + seg * 8) * 2),
                 A + (size_t)(bm0 + row) * K + k0 + seg * 8);
            cp16(sB + (uint32_t)((st * HSTAGE + row * HSTR + seg * 8) * 2),
                 W + (size_t)(bn0 + row) * K + k0 + seg * 8);
        }
        cp_commit();
    };

    issue(0, 0);
    issue(1, 1);
    issue(2, 2);

    const uint32_t a_lane_off = (uint32_t)(((wm * 64 + (lm & 1) * 8 + lj) * HSTR + (lm >> 1) * 8) * 2);
    const uint32_t b_lane_off = (uint32_t)(((wn * 32 + (lm >> 1) * 8 + lj) * HSTR + (lm & 1) * 8) * 2);

    int st = 0;
    for (int kt = 0; kt < KT; kt++) {
        if (kt < KT - 2) cp_wait<2>();
        else if (kt == KT - 2) cp_wait<1>();
        else cp_wait<0>();
        __syncthreads();
        const uint32_t aSt = sA + st * HSTAGE * 2;
        const uint32_t bSt = sB + st * HSTAGE * 2;

        #pragma unroll
        for (int kk = 0; kk < HGBK / 16; kk++) {
            uint32_t af[4][4], bf2[2][4];
            #pragma unroll
            for (int mi = 0; mi < 4; mi++)
                ldsm_x4(af[mi], aSt + a_lane_off + (uint32_t)((mi * 16 * HSTR + kk * 16) * 2));
            #pragma unroll
            for (int nip = 0; nip < 2; nip++)
                ldsm_x4(bf2[nip], bSt + b_lane_off + (uint32_t)((nip * 16 * HSTR + kk * 16) * 2));
            #pragma unroll
            for (int mi = 0; mi < 4; mi++)
                #pragma unroll
                for (int ni = 0; ni < 4; ni++)
                    mma_f16(acc[mi][ni], af[mi], &bf2[ni >> 1][(ni & 1) * 2]);
        }
        __syncthreads();
        if (kt + 3 < KT) issue(kt + 3, st);
        st = (st == 2) ? 0 : st + 1;
    }

    #pragma unroll
    for (int mi = 0; mi < 4; mi++) {
        int r0 = bm0 + wm * 64 + mi * 16 + g;
        #pragma unroll
        for (int ni = 0; ni < 4; ni++) {
            int col = bn0 + wn * 32 + ni * 8 + 2 * t4;
            float e0 = acc[mi][ni][0] * alpha;
            float e1 = acc[mi][ni][1] * alpha;
            float e2 = acc[mi][ni][2] * alpha;
            float e3 = acc[mi][ni][3] * alpha;
            if (mode == 0) {
                float b0 = bias[col], b1 = bias[col + 1];
                *reinterpret_cast<float2*>(Cf + (size_t)r0       * 512 + col) = make_float2(e0 + b0, e1 + b1);
                *reinterpret_cast<float2*>(Cf + (size_t)(r0 + 8) * 512 + col) = make_float2(e2 + b0, e3 + b1);
            } else if (mode == 1) {
                *reinterpret_cast<uint32_t*>(ChQ + (size_t)r0       * 512 + col) = pack_h2(e0, e1);
                *reinterpret_cast<uint32_t*>(ChQ + (size_t)(r0 + 8) * 512 + col) = pack_h2(e2, e3);
            } else {
                if (col < 512) {
                    *reinterpret_cast<uint32_t*>(ChK + (size_t)r0       * 512 + col) = pack_h2(e0, e1);
                    *reinterpret_cast<uint32_t*>(ChK + (size_t)(r0 + 8) * 512 + col) = pack_h2(e2, e3);
                } else {
                    int dg = col - 512;
                    int hh = dg >> 6;
                    int dd = dg & 63;
                    int bb = r0 >> 11;
                    int nn = r0 & 2047;
                    __half* vt = CvtH + (((size_t)(bb * H_ + hh) * HD_ + dd) * N_) + nn;
                    vt[0]      = __float2half_rn(e0);
                    vt[N_]     = __float2half_rn(e1);
                    vt[8]      = __float2half_rn(e2);
                    vt[N_ + 8] = __float2half_rn(e3);
                }
            }
        }
    }
}

__global__ void __launch_bounds__(256, 2)
qkv_h_kernel(const __half* __restrict__ xh, const __half* __restrict__ wqh, __half* __restrict__ qh,
             const __half* __restrict__ vfh, const __half* __restrict__ wkvh,
             __half* __restrict__ kh, __half* __restrict__ vth)
{
    int bid = blockIdx.x;
    if (bid < 128) {
        gemm_h_body(xh, wqh, VD_, SCALE_ * LOG2E_, 1,
                    nullptr, qh, nullptr, nullptr, nullptr,
                    (bid >> 2) * 128, (bid & 3) * 128);
    } else {
        bid -= 128;
        gemm_h_body(vfh, wkvh, LD_, 1.0f, 2,
                    nullptr, nullptr, kh, vth, nullptr,
                    (bid >> 3) * 128, (bid & 7) * 128);
    }
}

__global__ void __launch_bounds__(256, 2)
proj_h_kernel(const __half* __restrict__ aoh, const __half* __restrict__ wph,
              float* __restrict__ out, const float* __restrict__ bias)
{
    gemm_h_body(aoh, wph, HID_, 1.0f, 0,
                out, nullptr, nullptr, nullptr, bias,
                (blockIdx.x >> 2) * 128, (blockIdx.x & 3) * 128);
}

// ======================================================================
// Flash attention v11: all-fp16 MMAs, 2 CTAs/SM, ldmatrix fragments,
// Q fragments HOISTED (loaded once, 16 regs). Two 64-key halves per
// tile keep s/mask register pressure at 32+32.
// ======================================================================
#define AQ_STRH 72
#define AK_STRH 72
#define VT_STRH 136
#define A_OFQ 0
#define A_QBYTES (128 * AQ_STRH * 2)        // 18432
#define A_OFK A_QBYTES
#define A_KBYTES (128 * AK_STRH * 2)        // 18432
#define A_OFV (A_OFK + 2 * A_KBYTES)        // 55296
#define A_VBYTES (64 * VT_STRH * 2)         // 17408
#define ATTN_SMEM (A_OFV + 2 * A_VBYTES)    // 90112

__global__ void __launch_bounds__(256, 2)
attn_kernel(const __half* __restrict__ q, const __half* __restrict__ kx,
            const __half* __restrict__ vth, const float* __restrict__ mask,
            __half* __restrict__ outh)
{
    extern __shared__ char smc[];
    const uint32_t sbase = (uint32_t)__cvta_generic_to_shared(smc);

    const int tid  = threadIdx.x;
    const int lane = tid & 31;
    const int w    = tid >> 5;
    const int g    = lane >> 2;
    const int t4   = lane & 3;
    const int lm   = lane >> 3;
    const int lj   = lane & 7;
    const int b     = blockIdx.z;
    const int h     = blockIdx.y;
    const int mbase = blockIdx.x * 128;

    const __half* qb  = q   + ((size_t)(b * L_ + mbase)) * HID_ + h * HD_;
    const __half* kb  = kx  + ((size_t)b * N_) * HID_ + h * HD_;
    const __half* vtb = vth + (size_t)(b * H_ + h) * HD_ * N_;

    // ---- prologue: Q tile (fp16) ----
    #pragma unroll
    for (int i = 0; i < 4; i++) {
        int c   = tid + 256 * i;
        int row = c >> 3;
        int seg = c & 7;
        cp16(sbase + (uint32_t)(A_OFQ + (row * AQ_STRH + seg * 8) * 2),
             qb + (size_t)row * HID_ + seg * 8);
    }
    cp_commit();

    auto issueKV = [&](int nt, int st) {
        const size_t nb = (size_t)nt * 128;
        #pragma unroll
        for (int i = 0; i < 4; i++) {
            int c   = tid + 256 * i;
            int row = c >> 3;
            int seg = c & 7;
            cp16(sbase + (uint32_t)(A_OFK + st * A_KBYTES + (row * AK_STRH + seg * 8) * 2),
                 kb + (nb + row) * HID_ + seg * 8);
        }
        #pragma unroll
        for (int i = 0; i < 4; i++) {
            int c   = tid + 256 * i;
            int row = c >> 4;
            int seg = c & 15;
            cp16(sbase + (uint32_t)(A_OFV + st * A_VBYTES + (row * VT_STRH + seg * 8) * 2),
                 vtb + (size_t)row * N_ + nb + seg * 8);
        }
        cp_commit();
    };
    issueKV(0, 0);
    issueKV(1, 1);

    cp_wait<2>();
    __syncthreads();

    const int row0 = w * 16 + g;

    // per-lane ldmatrix offsets (bytes)
    const uint32_t q_lane = (uint32_t)(A_OFQ + ((w * 16 + (lm & 1) * 8 + lj) * AQ_STRH + (lm >> 1) * 8) * 2);
    const uint32_t k_lane = (uint32_t)((((lm >> 1) * 8 + lj) * AK_STRH + (lm & 1) * 8) * 2);
    const uint32_t v_lane = (uint32_t)((((lm >> 1) * 8 + lj) * VT_STRH + (lm & 1) * 8) * 2);

    // ---- hoisted Q fragments (16 regs, loaded once) ----
    uint32_t qa[4][4];
    #pragma unroll
    for (int ks = 0; ks < 4; ks++)
        ldsm_x4(qa[ks], sbase + q_lane + (uint32_t)(ks * 16 * 2));

    float l0 = 0.f, l1 = 0.f;
    float o[8][4];
    #pragma unroll
    for (int df = 0; df < 8; df++)
        #pragma unroll
        for (int j = 0; j < 4; j++) o[df][j] = 0.f;

    const float* mrow = mask + (((size_t)(b * H_ + h)) * L_ + mbase + row0) * N_ + 2 * t4;

    for (int nt = 0; nt < N_ / 128; nt++) {
        if (nt < 15) cp_wait<1>(); else cp_wait<0>();
        __syncthreads();
        const uint32_t sK = sbase + A_OFK + (nt & 1) * A_KBYTES;
        const uint32_t sV = sbase + A_OFV + (nt & 1) * A_VBYTES;

        #pragma unroll
        for (int kh = 0; kh < 2; kh++) {
            // ---- mask prefetch for this 64-key half ----
            float2 mk0[8], mk1[8];
            {
                const float* mp = mrow + (size_t)nt * 128 + kh * 64;
                #pragma unroll
                for (int nf = 0; nf < 8; nf++) {
                    mk0[nf] = *reinterpret_cast<const float2*>(mp + nf * 8);
                    mk1[nf] = *reinterpret_cast<const float2*>(mp + (size_t)8 * N_ + nf * 8);
                }
            }

            const uint32_t sKh = sK + (uint32_t)(kh * 64 * AK_STRH * 2) + k_lane;

            // ---- S = Q K^T over this half ----
            float s[8][4];
            #pragma unroll
            for (int nf = 0; nf < 8; nf++) {
                s[nf][0] = 0.f; s[nf][1] = 0.f; s[nf][2] = 0.f; s[nf][3] = 0.f;
            }
            #pragma unroll
            for (int ks = 0; ks < 4; ks++) {
                #pragma unroll
                for (int nfp = 0; nfp < 4; nfp++) {
                    uint32_t bf[4];
                    ldsm_x4(bf, sKh + (uint32_t)((nfp * 16 * AK_STRH + ks * 16) * 2));
                    mma_f16(s[2 * nfp],     qa[ks], &bf[0]);
                    mma_f16(s[2 * nfp + 1], qa[ks], &bf[2]);
                }
            }

            // ---- p = exp2(s + mask*log2e), accumulate l ----
            #pragma unroll
            for (int nf = 0; nf < 8; nf++) {
                s[nf][0] = ex2(fmaf(mk0[nf].x, LOG2E_, s[nf][0]));
                s[nf][1] = ex2(fmaf(mk0[nf].y, LOG2E_, s[nf][1]));
                s[nf][2] = ex2(fmaf(mk1[nf].x, LOG2E_, s[nf][2]));
                s[nf][3] = ex2(fmaf(mk1[nf].y, LOG2E_, s[nf][3]));
                l0 += s[nf][0] + s[nf][1];
                l1 += s[nf][2] + s[nf][3];
            }

            // ---- O += P V over this half ----
            #pragma unroll
            for (int j = 0; j < 4; j++) {
                uint32_t pa[4] = {
                    pack_h2(s[2*j][0],   s[2*j][1]),
                    pack_h2(s[2*j][2],   s[2*j][3]),
                    pack_h2(s[2*j+1][0], s[2*j+1][1]),
                    pack_h2(s[2*j+1][2], s[2*j+1][3])
                };
                const uint32_t sVk = sV + v_lane + (uint32_t)((kh * 4 + j) * 16 * 2);
                #pragma unroll
                for (int dfp = 0; dfp < 4; dfp++) {
                    uint32_t bf[4];
                    ldsm_x4(bf, sVk + (uint32_t)(dfp * 16 * VT_STRH * 2));
                    mma_f16(o[2 * dfp],     pa, &bf[0]);
                    mma_f16(o[2 * dfp + 1], pa, &bf[2]);
                }
            }
        }

        __syncthreads();
        if (nt + 2 < N_ / 128) issueKV(nt + 2, nt & 1);
    }

    l0 += __shfl_xor_sync(0xffffffffu, l0, 1);
    l0 += __shfl_xor_sync(0xffffffffu, l0, 2);
    l1 += __shfl_xor_sync(0xffffffffu, l1, 1);
    l1 += __shfl_xor_sync(0xffffffffu, l1, 2);
    float inv0 = 1.f / l0, inv1 = 1.f / l1;

    __half* ob = outh + ((size_t)(b * L_ + mbase + row0)) * HID_ + h * HD_;
    #pragma unroll
    for (int df = 0; df < 8; df++) {
        int col = df * 8 + 2 * t4;
        *reinterpret_cast<uint32_t*>(ob + col) =
            pack_h2(o[df][0] * inv0, o[df][1] * inv0);
        *reinterpret_cast<uint32_t*>(ob + (size_t)8 * HID_ + col) =
            pack_h2(o[df][2] * inv1, o[df][3] * inv1);
    }
}

// ======================================================================
extern "C" void kernel_launch(void* const* d_in, const int* in_sizes, int n_in,
                              void* d_out, int out_size)
{
    (void)in_sizes; (void)n_in; (void)out_size;
    const float* x     = (const float*)d_in[0];
    const float* vf    = (const float*)d_in[1];
    const float* mask  = (const float*)d_in[2];
    const float* Wq    = (const float*)d_in[3];
    const float* Wkv   = (const float*)d_in[4];
    const float* Wproj = (const float*)d_in[5];
    const float* bproj = (const float*)d_in[6];
    float* out = (float*)d_out;

    __half *qh, *kh, *vth, *aoh, *xh, *vfh, *wqh, *wkvh, *wph;
    cudaGetSymbolAddress((void**)&qh,   g_qh);
    cudaGetSymbolAddress((void**)&kh,   g_kh);
    cudaGetSymbolAddress((void**)&vth,  g_vth);
    cudaGetSymbolAddress((void**)&aoh,  g_aoh);
    cudaGetSymbolAddress((void**)&xh,   g_xh);
    cudaGetSymbolAddress((void**)&vfh,  g_vfh);
    cudaGetSymbolAddress((void**)&wqh,  g_wqh);
    cudaGetSymbolAddress((void**)&wkvh, g_wkvh);
    cudaGetSymbolAddress((void**)&wph,  g_wph);

    cudaFuncSetAttribute(qkv_h_kernel,  cudaFuncAttributeMaxDynamicSharedMemorySize, HGEMM_SMEM);
    cudaFuncSetAttribute(proj_h_kernel, cudaFuncAttributeMaxDynamicSharedMemorySize, HGEMM_SMEM);
    cudaFuncSetAttribute(attn_kernel,   cudaFuncAttributeMaxDynamicSharedMemorySize, ATTN_SMEM);

    // 0) round inputs/weights to fp16 once
    prepass_kernel<<<1184, 256>>>(
        (const float4*)x, (const float4*)vf, (const float4*)Wq,
        (const float4*)Wkv, (const float4*)Wproj,
        (uint2*)xh, (uint2*)vfh, (uint2*)wqh, (uint2*)wkvh, (uint2*)wph);

    // 1) fp16 projections: Q + KV (K fp16 row-major, V^T fp16)
    qkv_h_kernel<<<640, 256, HGEMM_SMEM>>>(xh, wqh, qh, vfh, wkvh, kh, vth);

    // 2) fused flash attention (all-fp16 MMAs, ldmatrix, hoisted Q)
    attn_kernel<<<dim3(L_ / 128, H_, B_), 256, ATTN_SMEM>>>(qh, kh, vth, mask, aoh);

    // 3) out = AO @ Wproj^T + bproj
    proj_h_kernel<<<128, 256, HGEMM_SMEM>>>(aoh, wph, out, bproj);
}

// round 16
// speedup vs baseline: 1.0417x; 1.0417x over previous
#include <cuda_runtime.h>
#include <cuda_fp16.h>
#include <cstdint>

// ---------------- problem constants ----------------
#define B_    4
#define L_    1024
#define N_    2048
#define VD_   512
#define LD_   768
#define HID_  512
#define H_    8
#define HD_   64
#define SCALE_ 0.125f
#define LOG2E_ 1.4426950408889634f

// ---------------- scratch ----------------
__device__ __half g_qh  [(size_t)B_ * L_ * HID_];
__device__ __half g_kh  [(size_t)B_ * N_ * HID_];
__device__ __half g_vth [(size_t)B_ * H_ * HD_ * N_];   // V^T [b][h][d][n]
__device__ __half g_aoh [(size_t)B_ * L_ * HID_];
__device__ __half g_xh  [(size_t)B_ * L_ * VD_];
__device__ __half g_vfh [(size_t)B_ * N_ * LD_];
__device__ __half g_wqh [(size_t)HID_ * VD_];
__device__ __half g_wkvh[(size_t)2 * HID_ * LD_];
__device__ __half g_wph [(size_t)VD_ * HID_];

// ---------------- helpers ----------------
__device__ __forceinline__ float ex2(float x) {
    float y;
    asm("ex2.approx.f32 %0, %1;" : "=f"(y) : "f"(x));
    return y;
}

__device__ __forceinline__ uint32_t pack_h2(float lo, float hi) {
    __half2 h = __floats2half2_rn(lo, hi);
    return *reinterpret_cast<uint32_t*>(&h);
}

__device__ __forceinline__ void mma_f16(float* c, const uint32_t* a, const uint32_t* b) {
    asm volatile(
        "mma.sync.aligned.m16n8k16.row.col.f32.f16.f16.f32 "
        "{%0,%1,%2,%3}, {%4,%5,%6,%7}, {%8,%9}, {%0,%1,%2,%3};"
        : "+f"(c[0]), "+f"(c[1]), "+f"(c[2]), "+f"(c[3])
        : "r"(a[0]), "r"(a[1]), "r"(a[2]), "r"(a[3]), "r"(b[0]), "r"(b[1]));
}

__device__ __forceinline__ void ldsm_x4(uint32_t* r, uint32_t saddr) {
    asm volatile("ldmatrix.sync.aligned.m8n8.x4.shared.b16 {%0,%1,%2,%3}, [%4];"
                 : "=r"(r[0]), "=r"(r[1]), "=r"(r[2]), "=r"(r[3]) : "r"(saddr));
}

__device__ __forceinline__ void cp16(uint32_t dst, const void* src) {
    asm volatile("cp.async.cg.shared.global [%0], [%1], 16;" :: "r"(dst), "l"(src));
}
__device__ __forceinline__ void cp_commit() { asm volatile("cp.async.commit_group;"); }
template <int Np>
__device__ __forceinline__ void cp_wait() {
    asm volatile("cp.async.wait_group %0;" :: "n"(Np) : "memory");
}

// ======================================================================
// Prepass: round inputs/weights to fp16 once.
// ======================================================================
#define PN0 524288
#define PN1 1572864
#define PN2 65536
#define PN3 196608
#define PN4 65536
#define PNT (PN0 + PN1 + PN2 + PN3 + PN4)

__global__ void __launch_bounds__(256)
prepass_kernel(const float4* __restrict__ x,  const float4* __restrict__ vf,
               const float4* __restrict__ wq, const float4* __restrict__ wkv,
               const float4* __restrict__ wp,
               uint2* __restrict__ xh,  uint2* __restrict__ vfh,
               uint2* __restrict__ wqh, uint2* __restrict__ wkvh,
               uint2* __restrict__ wph)
{
    for (int i = blockIdx.x * blockDim.x + threadIdx.x; i < PNT;
         i += gridDim.x * blockDim.x) {
        const float4* s; uint2* d; int off;
        if (i < PN0)                   { s = x;   d = xh;   off = i; }
        else if (i < PN0+PN1)          { s = vf;  d = vfh;  off = i - PN0; }
        else if (i < PN0+PN1+PN2)      { s = wq;  d = wqh;  off = i - PN0 - PN1; }
        else if (i < PN0+PN1+PN2+PN3)  { s = wkv; d = wkvh; off = i - PN0 - PN1 - PN2; }
        else                           { s = wp;  d = wph;  off = i - PN0 - PN1 - PN2 - PN3; }
        float4 v = s[off];
        uint2 o;
        o.x = pack_h2(v.x, v.y);
        o.y = pack_h2(v.z, v.w);
        d[off] = o;
    }
}

// ======================================================================
// fp16 GEMM: 128x128 tile, 64-half K-stages, cp.async 3-stage pipeline,
// m16n8k16, HSTR=72, ldmatrix fragments.
// mode 0: fp32 out + bias; 1: fp16 out; 2: KV split (K fp16 / V^T fp16).
// ======================================================================
#define HSTR 72
#define HGBK 64
#define HSTAGE (128 * HSTR)
#define HSTAGES 3
#define HGEMM_SMEM (HSTAGES * 2 * HSTAGE * 2)   // 110592 bytes

__device__ __forceinline__ void gemm_h_body(
    const __half* __restrict__ A, const __half* __restrict__ W,
    int K, float alpha, int mode,
    float* __restrict__ Cf, __half* __restrict__ ChQ,
    __half* __restrict__ ChK, __half* __restrict__ CvtH,
    const float* __restrict__ bias,
    int bm0, int bn0)
{
    extern __shared__ char smc[];
    const uint32_t sbase = (uint32_t)__cvta_generic_to_shared(smc);
    const uint32_t sA = sbase;
    const uint32_t sB = sbase + HSTAGES * HSTAGE * 2;

    const int tid  = threadIdx.x;
    const int lane = tid & 31;
    const int w    = tid >> 5;
    const int g    = lane >> 2;
    const int t4   = lane & 3;
    const int wm   = w >> 2;
    const int wn   = w & 3;
    const int KT   = K / HGBK;
    const int lm   = lane >> 3;
    const int lj   = lane & 7;

    float acc[4][4][4];
    #pragma unroll
    for (int mi = 0; mi < 4; mi++)
        #pragma unroll
        for (int ni = 0; ni < 4; ni++)
            #pragma unroll
            for (int j = 0; j < 4; j++) acc[mi][ni][j] = 0.f;

    auto issue = [&](int kt, int st) {
        const int k0 = kt * HGBK;
        #pragma unroll
        for (int i = 0; i < 4; i++) {
            int c   = tid + 256 * i;
            int row = c >> 3;
            int seg = c & 7;
            cp16(sA + (uint32_t)((st * HSTAGE + row * HSTR + seg * 8) * 2),
                 A + (size_t)(bm0 + row) * K + k0 + seg * 8);
            cp16(sB + (uint32_t)((st * HSTAGE + row * HSTR + seg * 8) * 2),
                 W + (size_t)(bn0 + row) * K + k0 + seg * 8);
        }
        cp_commit();
    };

    issue(0, 0);
    issue(1, 1);
    issue(2, 2);

    const uint32_t a_lane_off = (uint32_t)(((wm * 64 + (lm & 1) * 8 + lj) * HSTR + (lm >> 1) * 8) * 2);
    const uint32_t b_lane_off = (uint32_t)(((wn * 32 + (lm >> 1) * 8 + lj) * HSTR + (lm & 1) * 8) * 2);

    int st = 0;
    for (int kt = 0; kt < KT; kt++) {
        if (kt < KT - 2) cp_wait<2>();
        else if (kt == KT - 2) cp_wait<1>();
        else cp_wait<0>();
        __syncthreads();
        const uint32_t aSt = sA + st * HSTAGE * 2;
        const uint32_t bSt = sB + st * HSTAGE * 2;

        #pragma unroll
        for (int kk = 0; kk < HGBK / 16; kk++) {
            uint32_t af[4][4], bf2[2][4];
            #pragma unroll
            for (int mi = 0; mi < 4; mi++)
                ldsm_x4(af[mi], aSt + a_lane_off + (uint32_t)((mi * 16 * HSTR + kk * 16) * 2));
            #pragma unroll
            for (int nip = 0; nip < 2; nip++)
                ldsm_x4(bf2[nip], bSt + b_lane_off + (uint32_t)((nip * 16 * HSTR + kk * 16) * 2));
            #pragma unroll
            for (int mi = 0; mi < 4; mi++)
                #pragma unroll
                for (int ni = 0; ni < 4; ni++)
                    mma_f16(acc[mi][ni], af[mi], &bf2[ni >> 1][(ni & 1) * 2]);
        }
        __syncthreads();
        if (kt + 3 < KT) issue(kt + 3, st);
        st = (st == 2) ? 0 : st + 1;
    }

    #pragma unroll
    for (int mi = 0; mi < 4; mi++) {
        int r0 = bm0 + wm * 64 + mi * 16 + g;
        #pragma unroll
        for (int ni = 0; ni < 4; ni++) {
            int col = bn0 + wn * 32 + ni * 8 + 2 * t4;
            float e0 = acc[mi][ni][0] * alpha;
            float e1 = acc[mi][ni][1] * alpha;
            float e2 = acc[mi][ni][2] * alpha;
            float e3 = acc[mi][ni][3] * alpha;
            if (mode == 0) {
                float b0 = bias[col], b1 = bias[col + 1];
                *reinterpret_cast<float2*>(Cf + (size_t)r0       * 512 + col) = make_float2(e0 + b0, e1 + b1);
                *reinterpret_cast<float2*>(Cf + (size_t)(r0 + 8) * 512 + col) = make_float2(e2 + b0, e3 + b1);
            } else if (mode == 1) {
                *reinterpret_cast<uint32_t*>(ChQ + (size_t)r0       * 512 + col) = pack_h2(e0, e1);
                *reinterpret_cast<uint32_t*>(ChQ + (size_t)(r0 + 8) * 512 + col) = pack_h2(e2, e3);
            } else {
                if (col < 512) {
                    *reinterpret_cast<uint32_t*>(ChK + (size_t)r0       * 512 + col) = pack_h2(e0, e1);
                    *reinterpret_cast<uint32_t*>(ChK + (size_t)(r0 + 8) * 512 + col) = pack_h2(e2, e3);
                } else {
                    int dg = col - 512;
                    int hh = dg >> 6;
                    int dd = dg & 63;
                    int bb = r0 >> 11;
                    int nn = r0 & 2047;
                    __half* vt = CvtH + (((size_t)(bb * H_ + hh) * HD_ + dd) * N_) + nn;
                    vt[0]      = __float2half_rn(e0);
                    vt[N_]     = __float2half_rn(e1);
                    vt[8]      = __float2half_rn(e2);
                    vt[N_ + 8] = __float2half_rn(e3);
                }
            }
        }
    }
}

__global__ void __launch_bounds__(256, 2)
qkv_h_kernel(const __half* __restrict__ xh, const __half* __restrict__ wqh, __half* __restrict__ qh,
             const __half* __restrict__ vfh, const __half* __restrict__ wkvh,
             __half* __restrict__ kh, __half* __restrict__ vth)
{
    int bid = blockIdx.x;
    if (bid < 128) {
        gemm_h_body(xh, wqh, VD_, SCALE_ * LOG2E_, 1,
                    nullptr, qh, nullptr, nullptr, nullptr,
                    (bid >> 2) * 128, (bid & 3) * 128);
    } else {
        bid -= 128;
        gemm_h_body(vfh, wkvh, LD_, 1.0f, 2,
                    nullptr, nullptr, kh, vth, nullptr,
                    (bid >> 3) * 128, (bid & 7) * 128);
    }
}

__global__ void __launch_bounds__(256, 2)
proj_h_kernel(const __half* __restrict__ aoh, const __half* __restrict__ wph,
              float* __restrict__ out, const float* __restrict__ bias)
{
    gemm_h_body(aoh, wph, HID_, 1.0f, 0,
                out, nullptr, nullptr, nullptr, bias,
                (blockIdx.x >> 2) * 128, (blockIdx.x & 3) * 128);
}

// ======================================================================
// Flash attention v12 = R14 (per-ks Q ldmatrix, 2 CTAs/SM) + first-half
// mask loads hoisted ABOVE cp_wait (overlap DRAM latency with the wait).
// ======================================================================
#define AQ_STRH 72
#define AK_STRH 72
#define VT_STRH 136
#define A_OFQ 0
#define A_QBYTES (128 * AQ_STRH * 2)        // 18432
#define A_OFK A_QBYTES
#define A_KBYTES (128 * AK_STRH * 2)        // 18432
#define A_OFV (A_OFK + 2 * A_KBYTES)        // 55296
#define A_VBYTES (64 * VT_STRH * 2)         // 17408
#define ATTN_SMEM (A_OFV + 2 * A_VBYTES)    // 90112

__global__ void __launch_bounds__(256, 2)
attn_kernel(const __half* __restrict__ q, const __half* __restrict__ kx,
            const __half* __restrict__ vth, const float* __restrict__ mask,
            __half* __restrict__ outh)
{
    extern __shared__ char smc[];
    const uint32_t sbase = (uint32_t)__cvta_generic_to_shared(smc);

    const int tid  = threadIdx.x;
    const int lane = tid & 31;
    const int w    = tid >> 5;
    const int g    = lane >> 2;
    const int t4   = lane & 3;
    const int lm   = lane >> 3;
    const int lj   = lane & 7;
    const int b     = blockIdx.z;
    const int h     = blockIdx.y;
    const int mbase = blockIdx.x * 128;

    const __half* qb  = q   + ((size_t)(b * L_ + mbase)) * HID_ + h * HD_;
    const __half* kb  = kx  + ((size_t)b * N_) * HID_ + h * HD_;
    const __half* vtb = vth + (size_t)(b * H_ + h) * HD_ * N_;

    // ---- prologue: Q tile (fp16) ----
    #pragma unroll
    for (int i = 0; i < 4; i++) {
        int c   = tid + 256 * i;
        int row = c >> 3;
        int seg = c & 7;
        cp16(sbase + (uint32_t)(A_OFQ + (row * AQ_STRH + seg * 8) * 2),
             qb + (size_t)row * HID_ + seg * 8);
    }
    cp_commit();

    auto issueKV = [&](int nt, int st) {
        const size_t nb = (size_t)nt * 128;
        #pragma unroll
        for (int i = 0; i < 4; i++) {
            int c   = tid + 256 * i;
            int row = c >> 3;
            int seg = c & 7;
            cp16(sbase + (uint32_t)(A_OFK + st * A_KBYTES + (row * AK_STRH + seg * 8) * 2),
                 kb + (nb + row) * HID_ + seg * 8);
        }
        #pragma unroll
        for (int i = 0; i < 4; i++) {
            int c   = tid + 256 * i;
            int row = c >> 4;
            int seg = c & 15;
            cp16(sbase + (uint32_t)(A_OFV + st * A_VBYTES + (row * VT_STRH + seg * 8) * 2),
                 vtb + (size_t)row * N_ + nb + seg * 8);
        }
        cp_commit();
    };
    issueKV(0, 0);
    issueKV(1, 1);

    cp_wait<2>();
    __syncthreads();

    const int row0 = w * 16 + g;

    // per-lane ldmatrix offsets (bytes)
    const uint32_t q_lane = (uint32_t)(A_OFQ + ((w * 16 + (lm & 1) * 8 + lj) * AQ_STRH + (lm >> 1) * 8) * 2);
    const uint32_t k_lane = (uint32_t)((((lm >> 1) * 8 + lj) * AK_STRH + (lm & 1) * 8) * 2);
    const uint32_t v_lane = (uint32_t)((((lm >> 1) * 8 + lj) * VT_STRH + (lm & 1) * 8) * 2);

    float l0 = 0.f, l1 = 0.f;
    float o[8][4];
    #pragma unroll
    for (int df = 0; df < 8; df++)
        #pragma unroll
        for (int j = 0; j < 4; j++) o[df][j] = 0.f;

    const float* mrow = mask + (((size_t)(b * H_ + h)) * L_ + mbase + row0) * N_ + 2 * t4;

    // process one 64-key half: S (per-ks Q ldmatrix), softmax, PV
    auto half_body = [&](uint32_t sK, uint32_t sV, int kh,
                         const float2* mk0, const float2* mk1) {
        const uint32_t sKh = sK + (uint32_t)(kh * 64 * AK_STRH * 2) + k_lane;

        float s[8][4];
        #pragma unroll
        for (int nf = 0; nf < 8; nf++) {
            s[nf][0] = 0.f; s[nf][1] = 0.f; s[nf][2] = 0.f; s[nf][3] = 0.f;
        }
        #pragma unroll
        for (int ks = 0; ks < 4; ks++) {
            uint32_t qa[4];
            ldsm_x4(qa, sbase + q_lane + (uint32_t)(ks * 16 * 2));
            #pragma unroll
            for (int nfp = 0; nfp < 4; nfp++) {
                uint32_t bf[4];
                ldsm_x4(bf, sKh + (uint32_t)((nfp * 16 * AK_STRH + ks * 16) * 2));
                mma_f16(s[2 * nfp],     qa, &bf[0]);
                mma_f16(s[2 * nfp + 1], qa, &bf[2]);
            }
        }

        #pragma unroll
        for (int nf = 0; nf < 8; nf++) {
            s[nf][0] = ex2(fmaf(mk0[nf].x, LOG2E_, s[nf][0]));
            s[nf][1] = ex2(fmaf(mk0[nf].y, LOG2E_, s[nf][1]));
            s[nf][2] = ex2(fmaf(mk1[nf].x, LOG2E_, s[nf][2]));
            s[nf][3] = ex2(fmaf(mk1[nf].y, LOG2E_, s[nf][3]));
            l0 += s[nf][0] + s[nf][1];
            l1 += s[nf][2] + s[nf][3];
        }

        #pragma unroll
        for (int j = 0; j < 4; j++) {
            uint32_t pa[4] = {
                pack_h2(s[2*j][0],   s[2*j][1]),
                pack_h2(s[2*j][2],   s[2*j][3]),
                pack_h2(s[2*j+1][0], s[2*j+1][1]),
                pack_h2(s[2*j+1][2], s[2*j+1][3])
            };
            const uint32_t sVk = sV + v_lane + (uint32_t)((kh * 4 + j) * 16 * 2);
            #pragma unroll
            for (int dfp = 0; dfp < 4; dfp++) {
                uint32_t bf[4];
                ldsm_x4(bf, sVk + (uint32_t)(dfp * 16 * VT_STRH * 2));
                mma_f16(o[2 * dfp],     pa, &bf[0]);
                mma_f16(o[2 * dfp + 1], pa, &bf[2]);
            }
        }
    };

    for (int nt = 0; nt < N_ / 128; nt++) {
        const float* mp = mrow + (size_t)nt * 128;

        // ---- half-0 mask loads BEFORE the wait (overlap DRAM with wait) ----
        float2 mk0[8], mk1[8];
        #pragma unroll
        for (int nf = 0; nf < 8; nf++) {
            mk0[nf] = *reinterpret_cast<const float2*>(mp + nf * 8);
            mk1[nf] = *reinterpret_cast<const float2*>(mp + (size_t)8 * N_ + nf * 8);
        }

        if (nt < 15) cp_wait<1>(); else cp_wait<0>();
        __syncthreads();
        const uint32_t sK = sbase + A_OFK + (nt & 1) * A_KBYTES;
        const uint32_t sV = sbase + A_OFV + (nt & 1) * A_VBYTES;

        half_body(sK, sV, 0, mk0, mk1);

        // ---- half-1 mask loads (overlap with half-0 tail) ----
        #pragma unroll
        for (int nf = 0; nf < 8; nf++) {
            mk0[nf] = *reinterpret_cast<const float2*>(mp + 64 + nf * 8);
            mk1[nf] = *reinterpret_cast<const float2*>(mp + (size_t)8 * N_ + 64 + nf * 8);
        }
        half_body(sK, sV, 1, mk0, mk1);

        __syncthreads();
        if (nt + 2 < N_ / 128) issueKV(nt + 2, nt & 1);
    }

    l0 += __shfl_xor_sync(0xffffffffu, l0, 1);
    l0 += __shfl_xor_sync(0xffffffffu, l0, 2);
    l1 += __shfl_xor_sync(0xffffffffu, l1, 1);
    l1 += __shfl_xor_sync(0xffffffffu, l1, 2);
    float inv0 = 1.f / l0, inv1 = 1.f / l1;

    __half* ob = outh + ((size_t)(b * L_ + mbase + row0)) * HID_ + h * HD_;
    #pragma unroll
    for (int df = 0; df < 8; df++) {
        int col = df * 8 + 2 * t4;
        *reinterpret_cast<uint32_t*>(ob + col) =
            pack_h2(o[df][0] * inv0, o[df][1] * inv0);
        *reinterpret_cast<uint32_t*>(ob + (size_t)8 * HID_ + col) =
            pack_h2(o[df][2] * inv1, o[df][3] * inv1);
    }
}

// ======================================================================
extern "C" void kernel_launch(void* const* d_in, const int* in_sizes, int n_in,
                              void* d_out, int out_size)
{
    (void)in_sizes; (void)n_in; (void)out_size;
    const float* x     = (const float*)d_in[0];
    const float* vf    = (const float*)d_in[1];
    const float* mask  = (const float*)d_in[2];
    const float* Wq    = (const float*)d_in[3];
    const float* Wkv   = (const float*)d_in[4];
    const float* Wproj = (const float*)d_in[5];
    const float* bproj = (const float*)d_in[6];
    float* out = (float*)d_out;

    __half *qh, *kh, *vth, *aoh, *xh, *vfh, *wqh, *wkvh, *wph;
    cudaGetSymbolAddress((void**)&qh,   g_qh);
    cudaGetSymbolAddress((void**)&kh,   g_kh);
    cudaGetSymbolAddress((void**)&vth,  g_vth);
    cudaGetSymbolAddress((void**)&aoh,  g_aoh);
    cudaGetSymbolAddress((void**)&xh,   g_xh);
    cudaGetSymbolAddress((void**)&vfh,  g_vfh);
    cudaGetSymbolAddress((void**)&wqh,  g_wqh);
    cudaGetSymbolAddress((void**)&wkvh, g_wkvh);
    cudaGetSymbolAddress((void**)&wph,  g_wph);

    cudaFuncSetAttribute(qkv_h_kernel,  cudaFuncAttributeMaxDynamicSharedMemorySize, HGEMM_SMEM);
    cudaFuncSetAttribute(proj_h_kernel, cudaFuncAttributeMaxDynamicSharedMemorySize, HGEMM_SMEM);
    cudaFuncSetAttribute(attn_kernel,   cudaFuncAttributeMaxDynamicSharedMemorySize, ATTN_SMEM);

    // 0) round inputs/weights to fp16 once
    prepass_kernel<<<1184, 256>>>(
        (const float4*)x, (const float4*)vf, (const float4*)Wq,
        (const float4*)Wkv, (const float4*)Wproj,
        (uint2*)xh, (uint2*)vfh, (uint2*)wqh, (uint2*)wkvh, (uint2*)wph);

    // 1) fp16 projections: Q + KV (K fp16 row-major, V^T fp16)
    qkv_h_kernel<<<640, 256, HGEMM_SMEM>>>(xh, wqh, qh, vfh, wkvh, kh, vth);

    // 2) fused flash attention (R14 structure + hoisted mask loads)
    attn_kernel<<<dim3(L_ / 128, H_, B_), 256, ATTN_SMEM>>>(qh, kh, vth, mask, aoh);

    // 3) out = AO @ Wproj^T + bproj
    proj_h_kernel<<<128, 256, HGEMM_SMEM>>>(aoh, wph, out, bproj);
}

// round 17
// speedup vs baseline: 1.0765x; 1.0335x over previous
#include <cuda_runtime.h>
#include <cuda_fp16.h>
#include <cstdint>

// ---------------- problem constants ----------------
#define B_    4
#define L_    1024
#define N_    2048
#define VD_   512
#define LD_   768
#define HID_  512
#define H_    8
#define HD_   64
#define SCALE_ 0.125f
#define LOG2E_ 1.4426950408889634f

// ---------------- scratch ----------------
__device__ __half g_qh  [(size_t)B_ * L_ * HID_];
__device__ __half g_kh  [(size_t)B_ * N_ * HID_];
__device__ __half g_vth [(size_t)B_ * H_ * HD_ * N_];   // V^T [b][h][d][n]
__device__ __half g_aoh [(size_t)B_ * L_ * HID_];
__device__ __half g_xh  [(size_t)B_ * L_ * VD_];
__device__ __half g_vfh [(size_t)B_ * N_ * LD_];
__device__ __half g_wqh [(size_t)HID_ * VD_];
__device__ __half g_wkvh[(size_t)2 * HID_ * LD_];
__device__ __half g_wph [(size_t)VD_ * HID_];

// ---------------- helpers ----------------
__device__ __forceinline__ float ex2(float x) {
    float y;
    asm("ex2.approx.f32 %0, %1;" : "=f"(y) : "f"(x));
    return y;
}

__device__ __forceinline__ uint32_t pack_h2(float lo, float hi) {
    __half2 h = __floats2half2_rn(lo, hi);
    return *reinterpret_cast<uint32_t*>(&h);
}

__device__ __forceinline__ void mma_f16(float* c, const uint32_t* a, const uint32_t* b) {
    asm volatile(
        "mma.sync.aligned.m16n8k16.row.col.f32.f16.f16.f32 "
        "{%0,%1,%2,%3}, {%4,%5,%6,%7}, {%8,%9}, {%0,%1,%2,%3};"
        : "+f"(c[0]), "+f"(c[1]), "+f"(c[2]), "+f"(c[3])
        : "r"(a[0]), "r"(a[1]), "r"(a[2]), "r"(a[3]), "r"(b[0]), "r"(b[1]));
}

__device__ __forceinline__ void ldsm_x4(uint32_t* r, uint32_t saddr) {
    asm volatile("ldmatrix.sync.aligned.m8n8.x4.shared.b16 {%0,%1,%2,%3}, [%4];"
                 : "=r"(r[0]), "=r"(r[1]), "=r"(r[2]), "=r"(r[3]) : "r"(saddr));
}

__device__ __forceinline__ void cp16(uint32_t dst, const void* src) {
    asm volatile("cp.async.cg.shared.global [%0], [%1], 16;" :: "r"(dst), "l"(src));
}
__device__ __forceinline__ void cp_commit() { asm volatile("cp.async.commit_group;"); }
template <int Np>
__device__ __forceinline__ void cp_wait() {
    asm volatile("cp.async.wait_group %0;" :: "n"(Np) : "memory");
}

// ======================================================================
// Prepass: round inputs/weights to fp16 once.
// ======================================================================
#define PN0 524288
#define PN1 1572864
#define PN2 65536
#define PN3 196608
#define PN4 65536
#define PNT (PN0 + PN1 + PN2 + PN3 + PN4)

__global__ void __launch_bounds__(256)
prepass_kernel(const float4* __restrict__ x,  const float4* __restrict__ vf,
               const float4* __restrict__ wq, const float4* __restrict__ wkv,
               const float4* __restrict__ wp,
               uint2* __restrict__ xh,  uint2* __restrict__ vfh,
               uint2* __restrict__ wqh, uint2* __restrict__ wkvh,
               uint2* __restrict__ wph)
{
    for (int i = blockIdx.x * blockDim.x + threadIdx.x; i < PNT;
         i += gridDim.x * blockDim.x) {
        const float4* s; uint2* d; int off;
        if (i < PN0)                   { s = x;   d = xh;   off = i; }
        else if (i < PN0+PN1)          { s = vf;  d = vfh;  off = i - PN0; }
        else if (i < PN0+PN1+PN2)      { s = wq;  d = wqh;  off = i - PN0 - PN1; }
        else if (i < PN0+PN1+PN2+PN3)  { s = wkv; d = wkvh; off = i - PN0 - PN1 - PN2; }
        else                           { s = wp;  d = wph;  off = i - PN0 - PN1 - PN2 - PN3; }
        float4 v = s[off];
        uint2 o;
        o.x = pack_h2(v.x, v.y);
        o.y = pack_h2(v.z, v.w);
        d[off] = o;
    }
}

// ======================================================================
// fp16 GEMM, templated on M-tile (MT in {64,128}); N-tile fixed 128.
// 64-half K-stages, cp.async 2-stage, m16n8k16, HSTR=72, ldmatrix frags.
// MT=128 is byte-identical to the proven R14 body. 8 warps as 2x4;
// warp tile (MT/2) x 32.
// mode 0: fp32 out + bias; 1: fp16 out; 2: KV split (K fp16 / V^T fp16).
// ======================================================================
#define HSTR 72
#define HGBK 64
#define BSTG (128 * HSTR)                       // B halves per stage
#define GEMM_SMEM(MT) (2 * ((MT) + 128) * HSTR * 2)

template <int MT>
__device__ __forceinline__ void gemm_h_body(
    const __half* __restrict__ A, const __half* __restrict__ W,
    int K, float alpha, int mode,
    float* __restrict__ Cf, __half* __restrict__ ChQ,
    __half* __restrict__ ChK, __half* __restrict__ CvtH,
    const float* __restrict__ bias,
    int bm0, int bn0)
{
    constexpr int ASTG = MT * HSTR;             // A halves per stage
    constexpr int MI   = MT / 32;               // mi count per warp
    extern __shared__ char smc[];
    const uint32_t sbase = (uint32_t)__cvta_generic_to_shared(smc);
    const uint32_t sA = sbase;
    const uint32_t sB = sbase + 2 * ASTG * 2;

    const int tid  = threadIdx.x;
    const int lane = tid & 31;
    const int w    = tid >> 5;
    const int g    = lane >> 2;
    const int t4   = lane & 3;
    const int wm   = w >> 2;
    const int wn   = w & 3;
    const int KT   = K / HGBK;
    const int lm   = lane >> 3;
    const int lj   = lane & 7;

    float acc[MI][4][4];
    #pragma unroll
    for (int mi = 0; mi < MI; mi++)
        #pragma unroll
        for (int ni = 0; ni < 4; ni++)
            #pragma unroll
            for (int j = 0; j < 4; j++) acc[mi][ni][j] = 0.f;

    auto issue = [&](int kt, int st) {
        const int k0 = kt * HGBK;
        #pragma unroll
        for (int i = 0; i < MT / 32; i++) {       // A: MT rows x 8 segs
            int c   = tid + 256 * i;
            int row = c >> 3;
            int seg = c & 7;
            cp16(sA + (uint32_t)((st * ASTG + row * HSTR + seg * 8) * 2),
                 A + (size_t)(bm0 + row) * K + k0 + seg * 8);
        }
        #pragma unroll
        for (int i = 0; i < 4; i++) {             // B: 128 rows x 8 segs
            int c   = tid + 256 * i;
            int row = c >> 3;
            int seg = c & 7;
            cp16(sB + (uint32_t)((st * BSTG + row * HSTR + seg * 8) * 2),
                 W + (size_t)(bn0 + row) * K + k0 + seg * 8);
        }
        cp_commit();
    };

    issue(0, 0);
    issue(1, 1);

    const uint32_t a_lane_off = (uint32_t)(((wm * (MT / 2) + (lm & 1) * 8 + lj) * HSTR + (lm >> 1) * 8) * 2);
    const uint32_t b_lane_off = (uint32_t)(((wn * 32 + (lm >> 1) * 8 + lj) * HSTR + (lm & 1) * 8) * 2);

    for (int kt = 0; kt < KT; kt++) {
        if (kt < KT - 1) cp_wait<1>(); else cp_wait<0>();
        __syncthreads();
        const uint32_t aSt = sA + (kt & 1) * ASTG * 2;
        const uint32_t bSt = sB + (kt & 1) * BSTG * 2;

        #pragma unroll
        for (int kk = 0; kk < HGBK / 16; kk++) {
            uint32_t af[MI][4], bf2[2][4];
            #pragma unroll
            for (int mi = 0; mi < MI; mi++)
                ldsm_x4(af[mi], aSt + a_lane_off + (uint32_t)((mi * 16 * HSTR + kk * 16) * 2));
            #pragma unroll
            for (int nip = 0; nip < 2; nip++)
                ldsm_x4(bf2[nip], bSt + b_lane_off + (uint32_t)((nip * 16 * HSTR + kk * 16) * 2));
            #pragma unroll
            for (int mi = 0; mi < MI; mi++)
                #pragma unroll
                for (int ni = 0; ni < 4; ni++)
                    mma_f16(acc[mi][ni], af[mi], &bf2[ni >> 1][(ni & 1) * 2]);
        }
        __syncthreads();
        if (kt + 2 < KT) issue(kt + 2, kt & 1);
    }

    #pragma unroll
    for (int mi = 0; mi < MI; mi++) {
        int r0 = bm0 + wm * (MT / 2) + mi * 16 + g;
        #pragma unroll
        for (int ni = 0; ni < 4; ni++) {
            int col = bn0 + wn * 32 + ni * 8 + 2 * t4;
            float e0 = acc[mi][ni][0] * alpha;
            float e1 = acc[mi][ni][1] * alpha;
            float e2 = acc[mi][ni][2] * alpha;
            float e3 = acc[mi][ni][3] * alpha;
            if (mode == 0) {
                float b0 = bias[col], b1 = bias[col + 1];
                *reinterpret_cast<float2*>(Cf + (size_t)r0       * 512 + col) = make_float2(e0 + b0, e1 + b1);
                *reinterpret_cast<float2*>(Cf + (size_t)(r0 + 8) * 512 + col) = make_float2(e2 + b0, e3 + b1);
            } else if (mode == 1) {
                *reinterpret_cast<uint32_t*>(ChQ + (size_t)r0       * 512 + col) = pack_h2(e0, e1);
                *reinterpret_cast<uint32_t*>(ChQ + (size_t)(r0 + 8) * 512 + col) = pack_h2(e2, e3);
            } else {
                if (col < 512) {
                    *reinterpret_cast<uint32_t*>(ChK + (size_t)r0       * 512 + col) = pack_h2(e0, e1);
                    *reinterpret_cast<uint32_t*>(ChK + (size_t)(r0 + 8) * 512 + col) = pack_h2(e2, e3);
                } else {
                    int dg = col - 512;
                    int hh = dg >> 6;
                    int dd = dg & 63;
                    int bb = r0 >> 11;
                    int nn = r0 & 2047;
                    __half* vt = CvtH + (((size_t)(bb * H_ + hh) * HD_ + dd) * N_) + nn;
                    vt[0]      = __float2half_rn(e0);
                    vt[N_]     = __float2half_rn(e1);
                    vt[8]      = __float2half_rn(e2);
                    vt[N_ + 8] = __float2half_rn(e3);
                }
            }
        }
    }
}

// KV tiles (expensive, K=768) scheduled FIRST; Q tiles (K=512) form the tail.
__global__ void __launch_bounds__(256, 2)
qkv_h_kernel(const __half* __restrict__ xh, const __half* __restrict__ wqh, __half* __restrict__ qh,
             const __half* __restrict__ vfh, const __half* __restrict__ wkvh,
             __half* __restrict__ kh, __half* __restrict__ vth)
{
    int bid = blockIdx.x;
    if (bid < 512) {
        gemm_h_body<128>(vfh, wkvh, LD_, 1.0f, 2,
                         nullptr, nullptr, kh, vth, nullptr,
                         (bid >> 3) * 128, (bid & 7) * 128);
    } else {
        bid -= 512;
        gemm_h_body<128>(xh, wqh, VD_, SCALE_ * LOG2E_, 1,
                         nullptr, qh, nullptr, nullptr, nullptr,
                         (bid >> 2) * 128, (bid & 3) * 128);
    }
}

// proj: 64-row tiles -> 256 CTAs = one full wave at 2 CTAs/SM.
__global__ void __launch_bounds__(256, 2)
proj_h_kernel(const __half* __restrict__ aoh, const __half* __restrict__ wph,
              float* __restrict__ out, const float* __restrict__ bias)
{
    gemm_h_body<64>(aoh, wph, HID_, 1.0f, 0,
                    out, nullptr, nullptr, nullptr, bias,
                    (blockIdx.x >> 2) * 64, (blockIdx.x & 3) * 128);
}

// ======================================================================
// Flash attention v12 = R14 EXACT (per-ks Q ldmatrix, 2 CTAs/SM,
// ldmatrix K/V fragments, mask loads inside the half after cp_wait).
// ======================================================================
#define AQ_STRH 72
#define AK_STRH 72
#define VT_STRH 136
#define A_OFQ 0
#define A_QBYTES (128 * AQ_STRH * 2)        // 18432
#define A_OFK A_QBYTES
#define A_KBYTES (128 * AK_STRH * 2)        // 18432
#define A_OFV (A_OFK + 2 * A_KBYTES)        // 55296
#define A_VBYTES (64 * VT_STRH * 2)         // 17408
#define ATTN_SMEM (A_OFV + 2 * A_VBYTES)    // 90112

__global__ void __launch_bounds__(256, 2)
attn_kernel(const __half* __restrict__ q, const __half* __restrict__ kx,
            const __half* __restrict__ vth, const float* __restrict__ mask,
            __half* __restrict__ outh)
{
    extern __shared__ char smc[];
    const uint32_t sbase = (uint32_t)__cvta_generic_to_shared(smc);

    const int tid  = threadIdx.x;
    const int lane = tid & 31;
    const int w    = tid >> 5;
    const int g    = lane >> 2;
    const int t4   = lane & 3;
    const int lm   = lane >> 3;
    const int lj   = lane & 7;
    const int b     = blockIdx.z;
    const int h     = blockIdx.y;
    const int mbase = blockIdx.x * 128;

    const __half* qb  = q   + ((size_t)(b * L_ + mbase)) * HID_ + h * HD_;
    const __half* kb  = kx  + ((size_t)b * N_) * HID_ + h * HD_;
    const __half* vtb = vth + (size_t)(b * H_ + h) * HD_ * N_;

    // ---- prologue: Q tile (fp16) ----
    #pragma unroll
    for (int i = 0; i < 4; i++) {
        int c   = tid + 256 * i;
        int row = c >> 3;
        int seg = c & 7;
        cp16(sbase + (uint32_t)(A_OFQ + (row * AQ_STRH + seg * 8) * 2),
             qb + (size_t)row * HID_ + seg * 8);
    }
    cp_commit();

    auto issueKV = [&](int nt, int st) {
        const size_t nb = (size_t)nt * 128;
        #pragma unroll
        for (int i = 0; i < 4; i++) {
            int c   = tid + 256 * i;
            int row = c >> 3;
            int seg = c & 7;
            cp16(sbase + (uint32_t)(A_OFK + st * A_KBYTES + (row * AK_STRH + seg * 8) * 2),
                 kb + (nb + row) * HID_ + seg * 8);
        }
        #pragma unroll
        for (int i = 0; i < 4; i++) {
            int c   = tid + 256 * i;
            int row = c >> 4;
            int seg = c & 15;
            cp16(sbase + (uint32_t)(A_OFV + st * A_VBYTES + (row * VT_STRH + seg * 8) * 2),
                 vtb + (size_t)row * N_ + nb + seg * 8);
        }
        cp_commit();
    };
    issueKV(0, 0);
    issueKV(1, 1);

    cp_wait<2>();
    __syncthreads();

    const int row0 = w * 16 + g;

    const uint32_t q_lane = (uint32_t)(A_OFQ + ((w * 16 + (lm & 1) * 8 + lj) * AQ_STRH + (lm >> 1) * 8) * 2);
    const uint32_t k_lane = (uint32_t)((((lm >> 1) * 8 + lj) * AK_STRH + (lm & 1) * 8) * 2);
    const uint32_t v_lane = (uint32_t)((((lm >> 1) * 8 + lj) * VT_STRH + (lm & 1) * 8) * 2);

    float l0 = 0.f, l1 = 0.f;
    float o[8][4];
    #pragma unroll
    for (int df = 0; df < 8; df++)
        #pragma unroll
        for (int j = 0; j < 4; j++) o[df][j] = 0.f;

    const float* mrow = mask + (((size_t)(b * H_ + h)) * L_ + mbase + row0) * N_ + 2 * t4;

    for (int nt = 0; nt < N_ / 128; nt++) {
        if (nt < 15) cp_wait<1>(); else cp_wait<0>();
        __syncthreads();
        const uint32_t sK = sbase + A_OFK + (nt & 1) * A_KBYTES;
        const uint32_t sV = sbase + A_OFV + (nt & 1) * A_VBYTES;

        #pragma unroll
        for (int kh = 0; kh < 2; kh++) {
            // ---- mask prefetch for this 64-key half ----
            float2 mk0[8], mk1[8];
            {
                const float* mp = mrow + (size_t)nt * 128 + kh * 64;
                #pragma unroll
                for (int nf = 0; nf < 8; nf++) {
                    mk0[nf] = *reinterpret_cast<const float2*>(mp + nf * 8);
                    mk1[nf] = *reinterpret_cast<const float2*>(mp + (size_t)8 * N_ + nf * 8);
                }
            }

            const uint32_t sKh = sK + (uint32_t)(kh * 64 * AK_STRH * 2) + k_lane;

            // ---- S = Q K^T over this half ----
            float s[8][4];
            #pragma unroll
            for (int nf = 0; nf < 8; nf++) {
                s[nf][0] = 0.f; s[nf][1] = 0.f; s[nf][2] = 0.f; s[nf][3] = 0.f;
            }
            #pragma unroll
            for (int ks = 0; ks < 4; ks++) {
                uint32_t qa[4];
                ldsm_x4(qa, sbase + q_lane + (uint32_t)(ks * 16 * 2));
                #pragma unroll
                for (int nfp = 0; nfp < 4; nfp++) {
                    uint32_t bf[4];
                    ldsm_x4(bf, sKh + (uint32_t)((nfp * 16 * AK_STRH + ks * 16) * 2));
                    mma_f16(s[2 * nfp],     qa, &bf[0]);
                    mma_f16(s[2 * nfp + 1], qa, &bf[2]);
                }
            }

            // ---- p = exp2(s + mask*log2e), accumulate l ----
            #pragma unroll
            for (int nf = 0; nf < 8; nf++) {
                s[nf][0] = ex2(fmaf(mk0[nf].x, LOG2E_, s[nf][0]));
                s[nf][1] = ex2(fmaf(mk0[nf].y, LOG2E_, s[nf][1]));
                s[nf][2] = ex2(fmaf(mk1[nf].x, LOG2E_, s[nf][2]));
                s[nf][3] = ex2(fmaf(mk1[nf].y, LOG2E_, s[nf][3]));
                l0 += s[nf][0] + s[nf][1];
                l1 += s[nf][2] + s[nf][3];
            }

            // ---- O += P V over this half ----
            #pragma unroll
            for (int j = 0; j < 4; j++) {
                uint32_t pa[4] = {
                    pack_h2(s[2*j][0],   s[2*j][1]),
                    pack_h2(s[2*j][2],   s[2*j][3]),
                    pack_h2(s[2*j+1][0], s[2*j+1][1]),
                    pack_h2(s[2*j+1][2], s[2*j+1][3])
                };
                const uint32_t sVk = sV + v_lane + (uint32_t)((kh * 4 + j) * 16 * 2);
                #pragma unroll
                for (int dfp = 0; dfp < 4; dfp++) {
                    uint32_t bf[4];
                    ldsm_x4(bf, sVk + (uint32_t)(dfp * 16 * VT_STRH * 2));
                    mma_f16(o[2 * dfp],     pa, &bf[0]);
                    mma_f16(o[2 * dfp + 1], pa, &bf[2]);
                }
            }
        }

        __syncthreads();
        if (nt + 2 < N_ / 128) issueKV(nt + 2, nt & 1);
    }

    l0 += __shfl_xor_sync(0xffffffffu, l0, 1);
    l0 += __shfl_xor_sync(0xffffffffu, l0, 2);
    l1 += __shfl_xor_sync(0xffffffffu, l1, 1);
    l1 += __shfl_xor_sync(0xffffffffu, l1, 2);
    float inv0 = 1.f / l0, inv1 = 1.f / l1;

    __half* ob = outh + ((size_t)(b * L_ + mbase + row0)) * HID_ + h * HD_;
    #pragma unroll
    for (int df = 0; df < 8; df++) {
        int col = df * 8 + 2 * t4;
        *reinterpret_cast<uint32_t*>(ob + col) =
            pack_h2(o[df][0] * inv0, o[df][1] * inv0);
        *reinterpret_cast<uint32_t*>(ob + (size_t)8 * HID_ + col) =
            pack_h2(o[df][2] * inv1, o[df][3] * inv1);
    }
}

// ======================================================================
extern "C" void kernel_launch(void* const* d_in, const int* in_sizes, int n_in,
                              void* d_out, int out_size)
{
    (void)in_sizes; (void)n_in; (void)out_size;
    const float* x     = (const float*)d_in[0];
    const float* vf    = (const float*)d_in[1];
    const float* mask  = (const float*)d_in[2];
    const float* Wq    = (const float*)d_in[3];
    const float* Wkv   = (const float*)d_in[4];
    const float* Wproj = (const float*)d_in[5];
    const float* bproj = (const float*)d_in[6];
    float* out = (float*)d_out;

    __half *qh, *kh, *vth, *aoh, *xh, *vfh, *wqh, *wkvh, *wph;
    cudaGetSymbolAddress((void**)&qh,   g_qh);
    cudaGetSymbolAddress((void**)&kh,   g_kh);
    cudaGetSymbolAddress((void**)&vth,  g_vth);
    cudaGetSymbolAddress((void**)&aoh,  g_aoh);
    cudaGetSymbolAddress((void**)&xh,   g_xh);
    cudaGetSymbolAddress((void**)&vfh,  g_vfh);
    cudaGetSymbolAddress((void**)&wqh,  g_wqh);
    cudaGetSymbolAddress((void**)&wkvh, g_wkvh);
    cudaGetSymbolAddress((void**)&wph,  g_wph);

    cudaFuncSetAttribute(qkv_h_kernel,  cudaFuncAttributeMaxDynamicSharedMemorySize, GEMM_SMEM(128));
    cudaFuncSetAttribute(proj_h_kernel, cudaFuncAttributeMaxDynamicSharedMemorySize, GEMM_SMEM(64));
    cudaFuncSetAttribute(attn_kernel,   cudaFuncAttributeMaxDynamicSharedMemorySize, ATTN_SMEM);

    // 0) round inputs/weights to fp16 once
    prepass_kernel<<<1184, 256>>>(
        (const float4*)x, (const float4*)vf, (const float4*)Wq,
        (const float4*)Wkv, (const float4*)Wproj,
        (uint2*)xh, (uint2*)vfh, (uint2*)wqh, (uint2*)wkvh, (uint2*)wph);

    // 1) fp16 projections: KV tiles first (expensive), Q tiles in the tail
    qkv_h_kernel<<<640, 256, GEMM_SMEM(128)>>>(xh, wqh, qh, vfh, wkvh, kh, vth);

    // 2) fused flash attention (R14 exact)
    attn_kernel<<<dim3(L_ / 128, H_, B_), 256, ATTN_SMEM>>>(qh, kh, vth, mask, aoh);

    // 3) out = AO @ Wproj^T + bproj (64-row tiles, one full wave)
    proj_h_kernel<<<256, 256, GEMM_SMEM(64)>>>(aoh, wph, out, bproj);
}